// round 7
// baseline (speedup 1.0000x reference)
#include <cuda_runtime.h>
#include <stdint.h>

// Cl(8,0,0): 256 components, 1024 multivectors (4x256), out [3,1024,256].
// gp[i] = sum_j sign(j, j^i) * A[j] * B[j^i]
//   sign(j,k) = (-1)^{popc(j & pp(k))},  pp linear over XOR: pp(k)=pp(j)^pp(i)
//   wedge: j & ~i == 0 ;  inner: (j&i)==0 || (i&~j)==0
// Grid 1024 x 128 threads: block = 32 i (lanes) x 4 j-slice warps, G=8 batch
// elems, f32x2 math, 128-bit shared loads, smem tree reduction across warps.

#define NCOMP 256
#define G 8
#define BATCH_ELEMS 1024

typedef unsigned long long u64;

#define MUL2(out, a, b) \
    asm("mul.rn.f32x2 %0, %1, %2;" : "=l"(out) : "l"(a), "l"(b))
#define FMA2(out, a, b, c) \
    asm("fma.rn.f32x2 %0, %1, %2, %3;" : "=l"(out) : "l"(a), "l"(b), "l"(c))
#define ADD2(out, a, b) \
    asm("add.rn.f32x2 %0, %1, %2;" : "=l"(out) : "l"(a), "l"(b))

__device__ __forceinline__ u64 pack2(float x) {
    u64 r;
    asm("mov.b64 %0, {%1, %1};" : "=l"(r) : "f"(x));
    return r;
}
__device__ __forceinline__ float2 unpack2(u64 v) {
    float2 f;
    asm("mov.b64 {%0, %1}, %2;" : "=f"(f.x), "=f"(f.y) : "l"(v));
    return f;
}

__host__ __device__ __forceinline__ constexpr unsigned ppf(unsigned v) {
    unsigned x = v << 1;
    x ^= x << 1;
    x ^= x << 2;
    x ^= x << 4;
    return x & 0xffu;
}

// smem: phase 1: sA (256*8 f32 = 8192B) + sB (256*12 f32 = 12288B) = 20480B
//       phase 2 (reduction, aliased): 64 * 13 u64 = 6656B
#define SMEM_BYTES 20480
#define RSTRIDE 13

__global__ __launch_bounds__(128, 8) void clifford_kernel(
    const float* __restrict__ A,
    const float* __restrict__ B,
    float* __restrict__ out) {
    __shared__ __align__(16) char smem_raw[SMEM_BYTES];
    float* sA = (float*)smem_raw;             // [j*8 + g], rows 32B
    float* sB = (float*)(smem_raw + 8192);    // [k*12 + g], rows 48B, 16B aligned

    const int tid = threadIdx.x;              // 0..127
    const int lane = tid & 31;
    const int s = tid >> 5;                   // j-slice warp 0..3
    const int group = blockIdx.x >> 3;        // batch group (8 elems)
    const int iquad = blockIdx.x & 7;         // which 32 i-values
    const int base = group * G;
    const int i = iquad * 32 + lane;

    // Coalesced load of 8 batch elems x 256 comps for A and B
    #pragma unroll
    for (int r = 0; r < (NCOMP * G) / 128; ++r) {
        int idx = r * 128 + tid;
        int j = idx & (NCOMP - 1);
        int g = idx >> 8;
        sA[j * 8 + g] = A[(base + g) * NCOMP + j];
        sB[j * 12 + g] = B[(base + g) * NCOMP + j];
    }
    __syncthreads();

    u64 accg[4], accw[4], acci[4];
    #pragma unroll
    for (int p = 0; p < 4; ++p) { accg[p] = 0ull; accw[p] = 0ull; acci[p] = 0ull; }

    const int noti = ~i;
    const unsigned pp_i = ppf((unsigned)i);
    const int jbase = s * 64;

    #pragma unroll 1
    for (int o = 0; o < 4; ++o) {
        const int jo = jbase + o * 16;
        const unsigned m_o = ppf((unsigned)jo) ^ pp_i;  // pp(jo)^pp(i)
        const int koi = jo ^ i;

        #pragma unroll
        for (int u = 0; u < 16; ++u) {                  // u compile-time
            const int j = jo | u;
            const int k = koi ^ u;
            const unsigned ppk = m_o ^ ppf((unsigned)u);
            const unsigned par = (unsigned)__popc(j & (int)ppk) & 1u;
            const float sgn = __int_as_float(0x3f800000u | (par << 31));
            const float wf = ((j & noti) == 0) ? sgn : 0.0f;
            const float nf = (((j & i) == 0) | ((i & ~j) == 0)) ? sgn : 0.0f;
            const u64 s2 = pack2(sgn);
            const u64 w2 = pack2(wf);
            const u64 n2 = pack2(nf);

            const ulonglong2* ap = (const ulonglong2*)(sA + j * 8);
            const ulonglong2* bp = (const ulonglong2*)(sB + k * 12);
            const ulonglong2 a01 = ap[0];
            const ulonglong2 a23 = ap[1];
            const ulonglong2 b01 = bp[0];
            const ulonglong2 b23 = bp[1];

            u64 v0, v1, v2, v3;
            MUL2(v0, a01.x, b01.x);
            MUL2(v1, a01.y, b01.y);
            MUL2(v2, a23.x, b23.x);
            MUL2(v3, a23.y, b23.y);
            FMA2(accg[0], v0, s2, accg[0]);
            FMA2(accg[1], v1, s2, accg[1]);
            FMA2(accg[2], v2, s2, accg[2]);
            FMA2(accg[3], v3, s2, accg[3]);
            FMA2(accw[0], v0, w2, accw[0]);
            FMA2(accw[1], v1, w2, accw[1]);
            FMA2(accw[2], v2, w2, accw[2]);
            FMA2(accw[3], v3, w2, accw[3]);
            FMA2(acci[0], v0, n2, acci[0]);
            FMA2(acci[1], v1, n2, acci[1]);
            FMA2(acci[2], v2, n2, acci[2]);
            FMA2(acci[3], v3, n2, acci[3]);
        }
    }

    // Tree reduction across the 4 j-slice warps (smem aliased over sA/sB)
    __syncthreads();
    u64* red = (u64*)smem_raw;

    if (tid >= 64) {                               // warps 2,3 store
        u64* dst = red + (tid - 64) * RSTRIDE;
        #pragma unroll
        for (int p = 0; p < 4; ++p) {
            dst[p] = accg[p]; dst[4 + p] = accw[p]; dst[8 + p] = acci[p];
        }
    }
    __syncthreads();
    if (tid < 64) {                                // warps 0,1 add
        const u64* src = red + tid * RSTRIDE;
        #pragma unroll
        for (int p = 0; p < 4; ++p) {
            ADD2(accg[p], accg[p], src[p]);
            ADD2(accw[p], accw[p], src[4 + p]);
            ADD2(acci[p], acci[p], src[8 + p]);
        }
    }
    __syncthreads();
    if (tid >= 32 && tid < 64) {                   // warp 1 stores
        u64* dst = red + (tid - 32) * RSTRIDE;
        #pragma unroll
        for (int p = 0; p < 4; ++p) {
            dst[p] = accg[p]; dst[4 + p] = accw[p]; dst[8 + p] = acci[p];
        }
    }
    __syncthreads();
    if (tid < 32) {                                // warp 0 adds + writes
        const u64* src = red + tid * RSTRIDE;
        #pragma unroll
        for (int p = 0; p < 4; ++p) {
            ADD2(accg[p], accg[p], src[p]);
            ADD2(accw[p], accw[p], src[4 + p]);
            ADD2(acci[p], acci[p], src[8 + p]);
        }
        #pragma unroll
        for (int p = 0; p < 4; ++p) {
            float2 g = unpack2(accg[p]);
            float2 w = unpack2(accw[p]);
            float2 n = unpack2(acci[p]);
            const int be0 = base + 2 * p;
            out[(0 * BATCH_ELEMS + be0) * NCOMP + i] = g.x;
            out[(0 * BATCH_ELEMS + be0 + 1) * NCOMP + i] = g.y;
            out[(1 * BATCH_ELEMS + be0) * NCOMP + i] = w.x;
            out[(1 * BATCH_ELEMS + be0 + 1) * NCOMP + i] = w.y;
            out[(2 * BATCH_ELEMS + be0) * NCOMP + i] = n.x;
            out[(2 * BATCH_ELEMS + be0 + 1) * NCOMP + i] = n.y;
        }
    }
}

extern "C" void kernel_launch(void* const* d_in, const int* in_sizes, int n_in,
                              void* d_out, int out_size) {
    const float* A = (const float*)d_in[0];
    const float* B = (const float*)d_in[1];
    float* out = (float*)d_out;
    clifford_kernel<<<(BATCH_ELEMS / G) * 8, 128>>>(A, B, out);
}

// round 8
// speedup vs baseline: 1.2655x; 1.2655x over previous
#include <cuda_runtime.h>
#include <stdint.h>

// Cl(8,0,0): 256 components, 1024 multivectors (4x256), out [3,1024,256].
// gp[i] = sum_j sign(j, j^i) * A[j] * B[j^i]
//   sign(j,k) = (-1)^{popc(j & pp(k))},  pp linear over XOR: pp(k)=pp(j)^pp(i)
//   wedge: j & ~i == 0 ;  inner: (j&i)==0 || (i&~j)==0
// G=4 batch elems/thread, 512-thr blocks (128 i x 4 j-slices), 3 blocks/SM
// (48 warps) via launch_bounds(512,3). f32x2 math, 128-bit shared loads,
// smem tree reduction across the 4 j-slice warps-groups.

#define NCOMP 256
#define G 4
#define BATCH_ELEMS 1024

typedef unsigned long long u64;

#define MUL2(out, a, b) \
    asm("mul.rn.f32x2 %0, %1, %2;" : "=l"(out) : "l"(a), "l"(b))
#define FMA2(out, a, b, c) \
    asm("fma.rn.f32x2 %0, %1, %2, %3;" : "=l"(out) : "l"(a), "l"(b), "l"(c))
#define ADD2(out, a, b) \
    asm("add.rn.f32x2 %0, %1, %2;" : "=l"(out) : "l"(a), "l"(b))

__device__ __forceinline__ u64 pack2(float x) {
    u64 r;
    asm("mov.b64 %0, {%1, %1};" : "=l"(r) : "f"(x));
    return r;
}
__device__ __forceinline__ float2 unpack2(u64 v) {
    float2 f;
    asm("mov.b64 {%0, %1}, %2;" : "=f"(f.x), "=f"(f.y) : "l"(v));
    return f;
}

__host__ __device__ __forceinline__ constexpr unsigned ppf(unsigned v) {
    unsigned x = v << 1;
    x ^= x << 1;
    x ^= x << 2;
    x ^= x << 4;
    return x & 0xffu;
}

// smem: phase 1: sA (256*4 f32 = 4096B) + sB (256*12 f32 = 12288B) = 16384B
//       phase 2 (reduction, aliased): 256 threads * 7 u64 = 14336B
#define SMEM_BYTES 16384
#define RSTRIDE 7

__global__ __launch_bounds__(512, 3) void clifford_kernel(
    const float* __restrict__ A,
    const float* __restrict__ B,
    float* __restrict__ out) {
    __shared__ __align__(16) char smem_raw[SMEM_BYTES];
    float* sA = (float*)smem_raw;             // [j*4 + g], rows 16B
    float* sB = (float*)(smem_raw + 4096);    // [k*12 + g], rows 48B, 16B aligned
                                              // (stride 12: 3k mod 8 bijective on
                                              //  k low bits -> conflict-free LDS.128)

    const int tid = threadIdx.x;              // 0..511
    const int t = tid & 127;                  // i within half
    const int s = tid >> 7;                   // j-slice 0..3
    const int bb = blockIdx.x >> 1;           // batch group of 4
    const int ih = blockIdx.x & 1;
    const int base = bb * G;
    const int i = ih * 128 + t;

    // Coalesced load of 4 batch elems x 256 comps for A and B
    #pragma unroll
    for (int r = 0; r < (NCOMP * G) / 512; ++r) {
        int idx = r * 512 + tid;
        int j = idx & (NCOMP - 1);
        int g = idx >> 8;
        sA[j * 4 + g] = A[(base + g) * NCOMP + j];
        sB[j * 12 + g] = B[(base + g) * NCOMP + j];
    }
    __syncthreads();

    u64 accg[2], accw[2], acci[2];
    #pragma unroll
    for (int p = 0; p < 2; ++p) { accg[p] = 0ull; accw[p] = 0ull; acci[p] = 0ull; }

    const int noti = ~i;
    const unsigned pp_i = ppf((unsigned)i);
    const int jbase = s * 64;

    #pragma unroll 1
    for (int o = 0; o < 4; ++o) {
        const int jo = jbase + o * 16;
        const unsigned m_o = ppf((unsigned)jo) ^ pp_i;  // pp(jo)^pp(i)
        const int koi = jo ^ i;

        #pragma unroll
        for (int u = 0; u < 16; ++u) {                  // u compile-time
            const int j = jo | u;
            const int k = koi ^ u;
            const unsigned ppk = m_o ^ ppf((unsigned)u);
            const unsigned par = (unsigned)__popc(j & (int)ppk) & 1u;
            const float sgn = __int_as_float(0x3f800000u | (par << 31));
            const float wf = ((j & noti) == 0) ? sgn : 0.0f;
            const float nf = (((j & i) == 0) | ((i & ~j) == 0)) ? sgn : 0.0f;
            const u64 s2 = pack2(sgn);
            const u64 w2 = pack2(wf);
            const u64 n2 = pack2(nf);

            // One 128-bit load each: A broadcast row, B gather row
            const ulonglong2 a01 = *(const ulonglong2*)(sA + j * 4);
            const ulonglong2 b01 = *(const ulonglong2*)(sB + k * 12);

            u64 v0, v1;
            MUL2(v0, a01.x, b01.x);
            MUL2(v1, a01.y, b01.y);
            FMA2(accg[0], v0, s2, accg[0]);
            FMA2(accg[1], v1, s2, accg[1]);
            FMA2(accw[0], v0, w2, accw[0]);
            FMA2(accw[1], v1, w2, accw[1]);
            FMA2(acci[0], v0, n2, acci[0]);
            FMA2(acci[1], v1, n2, acci[1]);
        }
    }

    // Tree reduction across the 4 j-slices (smem aliased over sA/sB)
    __syncthreads();
    u64* red = (u64*)smem_raw;

    if (tid >= 256) {                              // slices 2,3 store
        u64* dst = red + (tid - 256) * RSTRIDE;
        #pragma unroll
        for (int p = 0; p < 2; ++p) {
            dst[p] = accg[p]; dst[2 + p] = accw[p]; dst[4 + p] = acci[p];
        }
    }
    __syncthreads();
    if (tid < 256) {                               // slices 0,1 add
        const u64* src = red + tid * RSTRIDE;
        #pragma unroll
        for (int p = 0; p < 2; ++p) {
            ADD2(accg[p], accg[p], src[p]);
            ADD2(accw[p], accw[p], src[2 + p]);
            ADD2(acci[p], acci[p], src[4 + p]);
        }
    }
    __syncthreads();
    if (tid >= 128 && tid < 256) {                 // slice 1 stores
        u64* dst = red + (tid - 128) * RSTRIDE;
        #pragma unroll
        for (int p = 0; p < 2; ++p) {
            dst[p] = accg[p]; dst[2 + p] = accw[p]; dst[4 + p] = acci[p];
        }
    }
    __syncthreads();
    if (tid < 128) {                               // slice 0 adds + writes
        const u64* src = red + tid * RSTRIDE;
        #pragma unroll
        for (int p = 0; p < 2; ++p) {
            ADD2(accg[p], accg[p], src[p]);
            ADD2(accw[p], accw[p], src[2 + p]);
            ADD2(acci[p], acci[p], src[4 + p]);
        }
        #pragma unroll
        for (int p = 0; p < 2; ++p) {
            float2 g = unpack2(accg[p]);
            float2 w = unpack2(accw[p]);
            float2 n = unpack2(acci[p]);
            const int be0 = base + 2 * p;
            out[(0 * BATCH_ELEMS + be0) * NCOMP + i] = g.x;
            out[(0 * BATCH_ELEMS + be0 + 1) * NCOMP + i] = g.y;
            out[(1 * BATCH_ELEMS + be0) * NCOMP + i] = w.x;
            out[(1 * BATCH_ELEMS + be0 + 1) * NCOMP + i] = w.y;
            out[(2 * BATCH_ELEMS + be0) * NCOMP + i] = n.x;
            out[(2 * BATCH_ELEMS + be0 + 1) * NCOMP + i] = n.y;
        }
    }
}

extern "C" void kernel_launch(void* const* d_in, const int* in_sizes, int n_in,
                              void* d_out, int out_size) {
    const float* A = (const float*)d_in[0];
    const float* B = (const float*)d_in[1];
    float* out = (float*)d_out;
    clifford_kernel<<<(BATCH_ELEMS / G) * 2, 512>>>(A, B, out);
}

// round 9
// speedup vs baseline: 1.4046x; 1.1099x over previous
#include <cuda_runtime.h>
#include <stdint.h>

// Cl(8,0,0): 256 components, 1024 multivectors (4x256), out [3,1024,256].
// gp[i] = sum_j sign(j, j^i) * A[j] * B[j^i]
//   sign(j,k) = (-1)^{popc(j & pp(k))}, pp linear over XOR =>
//   sign(j, j^i) = (-1)^{q(j)} * (-1)^{parity(j & pp(i))},  q(j)=parity(j&pp(j))
//   (-1)^{q(j)} is folded into sA at fill time.
//   wedge: j & ~i == 0 ;  inner: (j&i)==0 || (i&~j)==0
// Per-thread 16-bit LUTs over the low nibble u make per-u coefficients pure
// const-shift+LOP3. G=8 batch elems, 512-thr blocks (128 i x 4 j-slices),
// f32x2 math, 128-bit shared loads, smem tree reduction.

#define NCOMP 256
#define G 8
#define BATCH_ELEMS 1024

typedef unsigned long long u64;

#define MUL2(out, a, b) \
    asm("mul.rn.f32x2 %0, %1, %2;" : "=l"(out) : "l"(a), "l"(b))
#define FMA2(out, a, b, c) \
    asm("fma.rn.f32x2 %0, %1, %2, %3;" : "=l"(out) : "l"(a), "l"(b), "l"(c))
#define ADD2(out, a, b) \
    asm("add.rn.f32x2 %0, %1, %2;" : "=l"(out) : "l"(a), "l"(b))

__device__ __forceinline__ u64 pack2(unsigned w) {
    u64 r;
    asm("mov.b64 %0, {%1, %1};" : "=l"(r) : "r"(w));
    return r;
}
__device__ __forceinline__ float2 unpack2(u64 v) {
    float2 f;
    asm("mov.b64 {%0, %1}, %2;" : "=f"(f.x), "=f"(f.y) : "l"(v));
    return f;
}

__host__ __device__ __forceinline__ constexpr unsigned ppf(unsigned v) {
    unsigned x = v << 1;
    x ^= x << 1;
    x ^= x << 2;
    x ^= x << 4;
    return x & 0xffu;
}

// submask indicator word over u in 0..15: bit u set iff u subset of m (m 4-bit)
__device__ __forceinline__ unsigned submask16(unsigned m) {
    unsigned w = 1u;
    if (m & 1u) w |= w << 1;
    if (m & 2u) w |= w << 2;
    if (m & 4u) w |= w << 4;
    if (m & 8u) w |= w << 8;
    return w;
}
// supermask indicator: bit u set iff r subset of u (0 if r has bits >= 16)
__device__ __forceinline__ unsigned supmask16(unsigned r) {
    unsigned w = 0xFFFFu;
    if (r & 1u) w &= 0xAAAAu;
    if (r & 2u) w &= 0xCCCCu;
    if (r & 4u) w &= 0xF0F0u;
    if (r & 8u) w &= 0xFF00u;
    if (r & ~15u) w = 0u;
    return w;
}

// smem: phase 1: sA (256*8 f32 = 8192B) + sB (256*12 f32 = 12288B) = 20480B
//       phase 2 (reduction, aliased): 256 * 13 u64 = 26624B
#define SMEM_BYTES 26624
#define RSTRIDE 13

__global__ __launch_bounds__(512, 2) void clifford_kernel(
    const float* __restrict__ A,
    const float* __restrict__ B,
    float* __restrict__ out) {
    __shared__ __align__(16) char smem_raw[SMEM_BYTES];
    float* sA = (float*)smem_raw;             // [j*8 + g], (-1)^q(j) folded in
    float* sB = (float*)(smem_raw + 8192);    // [k*12 + g], rows 48B

    const int tid = threadIdx.x;              // 0..511
    const int t = tid & 127;
    const int s = tid >> 7;                   // j-slice 0..3
    const int bb = blockIdx.x >> 1;
    const int ih = blockIdx.x & 1;
    const int base = bb * G;
    const int i = ih * 128 + t;

    // Coalesced fill; fold (-1)^{q(j)} into A
    #pragma unroll
    for (int r = 0; r < (NCOMP * G) / 512; ++r) {
        int idx = r * 512 + tid;
        int j = idx & (NCOMP - 1);
        int g = idx >> 8;
        float a = A[(base + g) * NCOMP + j];
        unsigned q = (unsigned)__popc(j & (int)ppf((unsigned)j)) & 1u;
        sA[j * 8 + g] = __int_as_float(__float_as_int(a) ^ (int)(q << 31));
        sB[j * 12 + g] = B[(base + g) * NCOMP + j];
    }
    __syncthreads();

    u64 accg[4], accw[4], acci[4];
    #pragma unroll
    for (int p = 0; p < 4; ++p) { accg[p] = 0ull; accw[p] = 0ull; acci[p] = 0ull; }

    const int noti = ~i;
    const unsigned pp_i = ppf((unsigned)i);

    // Per-thread 16-bit LUTs over low nibble u
    unsigned lut_s = 0u;                       // bit u = parity(u & pp_i)
    if (pp_i & 1u) lut_s ^= 0xAAAAu;
    if (pp_i & 2u) lut_s ^= 0xCCCCu;
    if (pp_i & 4u) lut_s ^= 0xF0F0u;
    if (pp_i & 8u) lut_s ^= 0xFF00u;
    const unsigned lut_w = submask16((unsigned)i & 15u);     // u subset of i
    const unsigned lut_c1 = submask16((unsigned)noti & 15u); // (u & i)==0

    const int jbase = s * 64;

    #pragma unroll 1
    for (int o = 0; o < 4; ++o) {
        const int jo = jbase + o * 16;
        // per-o 16-bit coefficient words
        const unsigned pjo = (unsigned)__popc(jo & (int)pp_i) & 1u;
        const unsigned so_w = pjo ? (lut_s ^ 0xFFFFu) : lut_s;   // sign bits
        const unsigned w_w = ((jo & noti) == 0) ? lut_w : 0u;    // wedge bits
        const unsigned r_o = (unsigned)(i & ~jo);
        const unsigned n_w = (((jo & i) == 0) ? lut_c1 : 0u) | supmask16(r_o);
        const int koi = jo ^ i;

        #pragma unroll
        for (int u = 0; u < 16; ++u) {                  // u compile-time
            const int k = koi ^ u;
            // sign float bits: 0x3f800000 | (bit u of so_w)<<31
            const unsigned sb = (so_w << (31 - u)) & 0x80000000u;
            const unsigned sgnw = sb | 0x3f800000u;
            const unsigned wm = (unsigned)(((int)(w_w << (31 - u))) >> 31);
            const unsigned nm = (unsigned)(((int)(n_w << (31 - u))) >> 31);
            const u64 s2 = pack2(sgnw);
            const u64 w2 = pack2(sgnw & wm);
            const u64 n2 = pack2(sgnw & nm);

            const ulonglong2* ap = (const ulonglong2*)(sA + (jo | u) * 8);
            const ulonglong2* bp = (const ulonglong2*)(sB + k * 12);
            const ulonglong2 a01 = ap[0];
            const ulonglong2 a23 = ap[1];
            const ulonglong2 b01 = bp[0];
            const ulonglong2 b23 = bp[1];

            u64 v0, v1, v2, v3;
            MUL2(v0, a01.x, b01.x);
            MUL2(v1, a01.y, b01.y);
            MUL2(v2, a23.x, b23.x);
            MUL2(v3, a23.y, b23.y);
            FMA2(accg[0], v0, s2, accg[0]);
            FMA2(accg[1], v1, s2, accg[1]);
            FMA2(accg[2], v2, s2, accg[2]);
            FMA2(accg[3], v3, s2, accg[3]);
            FMA2(accw[0], v0, w2, accw[0]);
            FMA2(accw[1], v1, w2, accw[1]);
            FMA2(accw[2], v2, w2, accw[2]);
            FMA2(accw[3], v3, w2, accw[3]);
            FMA2(acci[0], v0, n2, acci[0]);
            FMA2(acci[1], v1, n2, acci[1]);
            FMA2(acci[2], v2, n2, acci[2]);
            FMA2(acci[3], v3, n2, acci[3]);
        }
    }

    // Tree reduction across the 4 j-slices (smem aliased over sA/sB)
    __syncthreads();
    u64* red = (u64*)smem_raw;

    if (tid >= 256) {
        u64* dst = red + (tid - 256) * RSTRIDE;
        #pragma unroll
        for (int p = 0; p < 4; ++p) {
            dst[p] = accg[p]; dst[4 + p] = accw[p]; dst[8 + p] = acci[p];
        }
    }
    __syncthreads();
    if (tid < 256) {
        const u64* src = red + tid * RSTRIDE;
        #pragma unroll
        for (int p = 0; p < 4; ++p) {
            ADD2(accg[p], accg[p], src[p]);
            ADD2(accw[p], accw[p], src[4 + p]);
            ADD2(acci[p], acci[p], src[8 + p]);
        }
    }
    __syncthreads();
    if (tid >= 128 && tid < 256) {
        u64* dst = red + (tid - 128) * RSTRIDE;
        #pragma unroll
        for (int p = 0; p < 4; ++p) {
            dst[p] = accg[p]; dst[4 + p] = accw[p]; dst[8 + p] = acci[p];
        }
    }
    __syncthreads();
    if (tid < 128) {
        const u64* src = red + tid * RSTRIDE;
        #pragma unroll
        for (int p = 0; p < 4; ++p) {
            ADD2(accg[p], accg[p], src[p]);
            ADD2(accw[p], accw[p], src[4 + p]);
            ADD2(acci[p], acci[p], src[8 + p]);
        }
        #pragma unroll
        for (int p = 0; p < 4; ++p) {
            float2 g = unpack2(accg[p]);
            float2 w = unpack2(accw[p]);
            float2 n = unpack2(acci[p]);
            const int be0 = base + 2 * p;
            out[(0 * BATCH_ELEMS + be0) * NCOMP + i] = g.x;
            out[(0 * BATCH_ELEMS + be0 + 1) * NCOMP + i] = g.y;
            out[(1 * BATCH_ELEMS + be0) * NCOMP + i] = w.x;
            out[(1 * BATCH_ELEMS + be0 + 1) * NCOMP + i] = w.y;
            out[(2 * BATCH_ELEMS + be0) * NCOMP + i] = n.x;
            out[(2 * BATCH_ELEMS + be0 + 1) * NCOMP + i] = n.y;
        }
    }
}

extern "C" void kernel_launch(void* const* d_in, const int* in_sizes, int n_in,
                              void* d_out, int out_size) {
    const float* A = (const float*)d_in[0];
    const float* B = (const float*)d_in[1];
    float* out = (float*)d_out;
    clifford_kernel<<<(BATCH_ELEMS / G) * 2, 512>>>(A, B, out);
}

// round 10
// speedup vs baseline: 1.5917x; 1.1332x over previous
#include <cuda_runtime.h>
#include <stdint.h>

// Cl(8,0,0): 256 comps, 1024 multivectors (4x256), out [3,1024,256].
// XOR-paired 2x2 tiling with d=128: pairs {(i,j),(i,j^d),(i^d,j),(i^d,j^d)}
// share B rows {k, k^d}, halving smem gather traffic and LDS issue.
//   sign(j,j^i) = (-1)^{q(j)} * (-1)^{parity(j & pp(i))}  (q folded into sA)
//   pp(i^128) == pp(i) mod 256 -> sign(i',j) = sign(i,j); j' adds const bit h7.
//   wedge(i,j)=w0, wedge(i,j')=0, wedge(i',j)=wedge(i',j')=w0  (i<128, j<128)
//   inner: c1=(j&i==0), c2=(i subset j); n(i,*)=c1|c2, n(i',j)=c1, n(i',j')=c2.
// G=4 batch elems, 512-thr blocks (128 i x 4 j-slices), f32x2 math,
// smem tree reduction across slices.

#define NCOMP 256
#define G 4
#define BATCH_ELEMS 1024

typedef unsigned long long u64;

#define MUL2(out, a, b) \
    asm("mul.rn.f32x2 %0, %1, %2;" : "=l"(out) : "l"(a), "l"(b))
#define FMA2(out, a, b, c) \
    asm("fma.rn.f32x2 %0, %1, %2, %3;" : "=l"(out) : "l"(a), "l"(b), "l"(c))
#define ADD2(out, a, b) \
    asm("add.rn.f32x2 %0, %1, %2;" : "=l"(out) : "l"(a), "l"(b))

__device__ __forceinline__ u64 pack2(unsigned w) {
    u64 r;
    asm("mov.b64 %0, {%1, %1};" : "=l"(r) : "r"(w));
    return r;
}
__device__ __forceinline__ float2 unpack2(u64 v) {
    float2 f;
    asm("mov.b64 {%0, %1}, %2;" : "=f"(f.x), "=f"(f.y) : "l"(v));
    return f;
}

__host__ __device__ __forceinline__ constexpr unsigned ppf(unsigned v) {
    unsigned x = v << 1;
    x ^= x << 1;
    x ^= x << 2;
    x ^= x << 4;
    return x & 0xffu;
}

__device__ __forceinline__ unsigned submask16(unsigned m) {
    unsigned w = 1u;
    if (m & 1u) w |= w << 1;
    if (m & 2u) w |= w << 2;
    if (m & 4u) w |= w << 4;
    if (m & 8u) w |= w << 8;
    return w;
}
__device__ __forceinline__ unsigned supmask16(unsigned r) {
    unsigned w = 0xFFFFu;
    if (r & 1u) w &= 0xAAAAu;
    if (r & 2u) w &= 0xCCCCu;
    if (r & 4u) w &= 0xF0F0u;
    if (r & 8u) w &= 0xFF00u;
    if (r & ~15u) w = 0u;
    return w;
}

// smem: phase 1: sA (256*4 f32 = 4096B) + sB (256*4 f32 = 4096B) = 8192B
//       phase 2 (reduction, aliased): 256 * 13 u64 = 26624B
#define SMEM_BYTES 26624
#define RSTRIDE 13

__global__ __launch_bounds__(512, 2) void clifford_kernel(
    const float* __restrict__ A,
    const float* __restrict__ B,
    float* __restrict__ out) {
    __shared__ __align__(16) char smem_raw[SMEM_BYTES];
    float* sA = (float*)smem_raw;             // [j*4 + g], (-1)^q(j) folded in
    float* sB = (float*)(smem_raw + 4096);    // [k*4 + g], 16B rows

    const int tid = threadIdx.x;              // 0..511
    const int iL = tid & 127;                 // i (low); i' = iL + 128
    const int s = tid >> 7;                   // j-slice 0..3
    const int base = blockIdx.x * G;

    // Coalesced fill; fold (-1)^{q(j)} into A
    #pragma unroll
    for (int r = 0; r < (NCOMP * G) / 512; ++r) {
        int idx = r * 512 + tid;
        int j = idx & (NCOMP - 1);
        int g = idx >> 8;
        float a = A[(base + g) * NCOMP + j];
        unsigned q = (unsigned)__popc(j & (int)ppf((unsigned)j)) & 1u;
        sA[j * 4 + g] = __int_as_float(__float_as_int(a) ^ (int)(q << 31));
        sB[j * 4 + g] = B[(base + g) * NCOMP + j];
    }
    __syncthreads();

    const int i = iL;
    const int noti = ~i;
    const unsigned pp_i = ppf((unsigned)i);
    const unsigned h7s = ((pp_i >> 7) & 1u) << 31;   // sign flip for j -> j^128

    // Per-thread 16-bit LUTs over low nibble u
    unsigned lut_s = 0u;                             // bit u = parity(u & pp_i)
    if (pp_i & 1u) lut_s ^= 0xAAAAu;
    if (pp_i & 2u) lut_s ^= 0xCCCCu;
    if (pp_i & 4u) lut_s ^= 0xF0F0u;
    if (pp_i & 8u) lut_s ^= 0xFF00u;
    const unsigned lut_w = submask16((unsigned)i & 15u);     // u subset of i
    const unsigned lut_c1 = submask16((unsigned)noti & 15u); // (u & i)==0

    // Accumulators: [i | i'] x [gp, we, in] x 2 f32x2
    u64 ag[2], aw[2], an[2], bg[2], bw[2], bn[2];
    #pragma unroll
    for (int p = 0; p < 2; ++p) {
        ag[p] = 0ull; aw[p] = 0ull; an[p] = 0ull;
        bg[p] = 0ull; bw[p] = 0ull; bn[p] = 0ull;
    }

    const int jsl = s * 32;                   // rep base: j in [32s, 32s+32)

    #pragma unroll 1
    for (int o = 0; o < 2; ++o) {
        const int jo = jsl + o * 16;          // bit7 = 0
        const unsigned pjo = (unsigned)__popc(jo & (int)pp_i) & 1u;
        const unsigned so_w = pjo ? (lut_s ^ 0xFFFFu) : lut_s;   // sign bits
        const unsigned w_w = ((jo & noti) == 0) ? lut_w : 0u;    // wedge
        const unsigned c1_w = ((jo & i) == 0) ? lut_c1 : 0u;     // (j&i)==0
        const unsigned c2_w = supmask16((unsigned)(i & ~jo));    // i subset j
        const int koi = jo ^ i;               // bit7 = 0

        #pragma unroll
        for (int u = 0; u < 16; ++u) {        // u compile-time
            const int j = jo | u;
            const int k = koi ^ u;
            const unsigned sb = (so_w << (31 - u)) & 0x80000000u;
            const unsigned s0w = sb | 0x3f800000u;               // sign (i,j),(i',j)
            const unsigned s1w = s0w ^ h7s;                      // sign (i,j'),(i',j')
            const unsigned wm = (unsigned)(((int)(w_w << (31 - u))) >> 31);
            const unsigned c1m = (unsigned)(((int)(c1_w << (31 - u))) >> 31);
            const unsigned c2m = (unsigned)(((int)(c2_w << (31 - u))) >> 31);
            const unsigned n0m = c1m | c2m;

            const u64 s0 = pack2(s0w);
            const u64 s1 = pack2(s1w);
            const u64 ws0 = pack2(s0w & wm);
            const u64 ws1 = pack2(s1w & wm);
            const u64 ns0 = pack2(s0w & n0m);
            const u64 ns1 = pack2(s1w & n0m);
            const u64 c1s0 = pack2(s0w & c1m);
            const u64 c2s1 = pack2(s1w & c2m);

            // rows: a0 = A[j], a1 = A[j+128]; b0 = B[k], b1 = B[k+128]
            const ulonglong2 a0 = *(const ulonglong2*)(sA + j * 4);
            const ulonglong2 a1 = *(const ulonglong2*)(sA + (j + 128) * 4);
            const ulonglong2 b0 = *(const ulonglong2*)(sB + k * 4);
            const ulonglong2 b1 = *(const ulonglong2*)(sB + (k + 128) * 4);

            #pragma unroll
            for (int p = 0; p < 2; ++p) {
                const u64 a0p = p ? a0.y : a0.x;
                const u64 a1p = p ? a1.y : a1.x;
                const u64 b0p = p ? b0.y : b0.x;
                const u64 b1p = p ? b1.y : b1.x;
                u64 v00, v11, v01, v10;
                MUL2(v00, a0p, b0p);   // (i, j)
                MUL2(v11, a1p, b1p);   // (i, j')
                MUL2(v01, a0p, b1p);   // (i', j)
                MUL2(v10, a1p, b0p);   // (i', j')
                // i outputs
                FMA2(ag[p], v00, s0, ag[p]);
                FMA2(ag[p], v11, s1, ag[p]);
                FMA2(aw[p], v00, ws0, aw[p]);          // wedge(i,j') = 0
                FMA2(an[p], v00, ns0, an[p]);
                FMA2(an[p], v11, ns1, an[p]);
                // i' outputs
                FMA2(bg[p], v01, s0, bg[p]);
                FMA2(bg[p], v10, s1, bg[p]);
                FMA2(bw[p], v01, ws0, bw[p]);
                FMA2(bw[p], v10, ws1, bw[p]);
                FMA2(bn[p], v01, c1s0, bn[p]);
                FMA2(bn[p], v10, c2s1, bn[p]);
            }
        }
    }

    // Tree reduction across the 4 j-slices (smem aliased over sA/sB)
    __syncthreads();
    u64* red = (u64*)smem_raw;

    if (tid >= 256) {
        u64* dst = red + (tid - 256) * RSTRIDE;
        #pragma unroll
        for (int p = 0; p < 2; ++p) {
            dst[p] = ag[p]; dst[2 + p] = aw[p]; dst[4 + p] = an[p];
            dst[6 + p] = bg[p]; dst[8 + p] = bw[p]; dst[10 + p] = bn[p];
        }
    }
    __syncthreads();
    if (tid < 256) {
        const u64* src = red + tid * RSTRIDE;
        #pragma unroll
        for (int p = 0; p < 2; ++p) {
            ADD2(ag[p], ag[p], src[p]);
            ADD2(aw[p], aw[p], src[2 + p]);
            ADD2(an[p], an[p], src[4 + p]);
            ADD2(bg[p], bg[p], src[6 + p]);
            ADD2(bw[p], bw[p], src[8 + p]);
            ADD2(bn[p], bn[p], src[10 + p]);
        }
    }
    __syncthreads();
    if (tid >= 128 && tid < 256) {
        u64* dst = red + (tid - 128) * RSTRIDE;
        #pragma unroll
        for (int p = 0; p < 2; ++p) {
            dst[p] = ag[p]; dst[2 + p] = aw[p]; dst[4 + p] = an[p];
            dst[6 + p] = bg[p]; dst[8 + p] = bw[p]; dst[10 + p] = bn[p];
        }
    }
    __syncthreads();
    if (tid < 128) {
        const u64* src = red + tid * RSTRIDE;
        #pragma unroll
        for (int p = 0; p < 2; ++p) {
            ADD2(ag[p], ag[p], src[p]);
            ADD2(aw[p], aw[p], src[2 + p]);
            ADD2(an[p], an[p], src[4 + p]);
            ADD2(bg[p], bg[p], src[6 + p]);
            ADD2(bw[p], bw[p], src[8 + p]);
            ADD2(bn[p], bn[p], src[10 + p]);
        }
        const int ihi = i + 128;
        #pragma unroll
        for (int p = 0; p < 2; ++p) {
            const int be0 = base + 2 * p;
            float2 g = unpack2(ag[p]);
            float2 w = unpack2(aw[p]);
            float2 n = unpack2(an[p]);
            out[(0 * BATCH_ELEMS + be0) * NCOMP + i] = g.x;
            out[(0 * BATCH_ELEMS + be0 + 1) * NCOMP + i] = g.y;
            out[(1 * BATCH_ELEMS + be0) * NCOMP + i] = w.x;
            out[(1 * BATCH_ELEMS + be0 + 1) * NCOMP + i] = w.y;
            out[(2 * BATCH_ELEMS + be0) * NCOMP + i] = n.x;
            out[(2 * BATCH_ELEMS + be0 + 1) * NCOMP + i] = n.y;
            g = unpack2(bg[p]);
            w = unpack2(bw[p]);
            n = unpack2(bn[p]);
            out[(0 * BATCH_ELEMS + be0) * NCOMP + ihi] = g.x;
            out[(0 * BATCH_ELEMS + be0 + 1) * NCOMP + ihi] = g.y;
            out[(1 * BATCH_ELEMS + be0) * NCOMP + ihi] = w.x;
            out[(1 * BATCH_ELEMS + be0 + 1) * NCOMP + ihi] = w.y;
            out[(2 * BATCH_ELEMS + be0) * NCOMP + ihi] = n.x;
            out[(2 * BATCH_ELEMS + be0 + 1) * NCOMP + ihi] = n.y;
        }
    }
}

extern "C" void kernel_launch(void* const* d_in, const int* in_sizes, int n_in,
                              void* d_out, int out_size) {
    const float* A = (const float*)d_in[0];
    const float* B = (const float*)d_in[1];
    float* out = (float*)d_out;
    clifford_kernel<<<BATCH_ELEMS / G, 512>>>(A, B, out);
}

// round 11
// speedup vs baseline: 1.9533x; 1.2272x over previous
#include <cuda_runtime.h>
#include <stdint.h>

// Cl(8,0,0): 256 comps, 1024 multivectors (4x256), out [3,1024,256].
// 4x4 XOR tiling on bits 6,7: thread covers outputs {i, i^64, i^128, i^192}
// and summand variants {j, j^64, j^128, j^192}; 16 products per 4 A + 4 B rows.
// sign(j_n -> i_m) = q(j_n) [folded into sA] ^ P(j) [coefficient]
//                    ^ par(i)(b6^b7)(hi) [folded into A regs]
//                    ^ b7(hi)b6(hi) [A regs] ^ b7(hi)b6(hv) [B-row variants]
// wedge/inner high-bit conditions are compile-time per (hi,hv).
// G=4 batch elems, 256-thr blocks (64 iL x 4 j-slices), f32x2 math,
// smem tree reduction across slices.

#define NCOMP 256
#define G 4
#define BATCH_ELEMS 1024

typedef unsigned long long u64;

#define MUL2(out, a, b) \
    asm("mul.rn.f32x2 %0, %1, %2;" : "=l"(out) : "l"(a), "l"(b))
#define FMA2(out, a, b, c) \
    asm("fma.rn.f32x2 %0, %1, %2, %3;" : "=l"(out) : "l"(a), "l"(b), "l"(c))
#define ADD2(out, a, b) \
    asm("add.rn.f32x2 %0, %1, %2;" : "=l"(out) : "l"(a), "l"(b))

__device__ __forceinline__ u64 pack2(unsigned w) {
    u64 r;
    asm("mov.b64 %0, {%1, %1};" : "=l"(r) : "r"(w));
    return r;
}
__device__ __forceinline__ float2 unpack2(u64 v) {
    float2 f;
    asm("mov.b64 {%0, %1}, %2;" : "=f"(f.x), "=f"(f.y) : "l"(v));
    return f;
}

__host__ __device__ __forceinline__ constexpr unsigned ppf(unsigned v) {
    unsigned x = v << 1;
    x ^= x << 1;
    x ^= x << 2;
    x ^= x << 4;
    return x & 0xffu;
}

__device__ __forceinline__ unsigned submask16(unsigned m) {
    unsigned w = 1u;
    if (m & 1u) w |= w << 1;
    if (m & 2u) w |= w << 2;
    if (m & 4u) w |= w << 4;
    if (m & 8u) w |= w << 8;
    return w;
}
__device__ __forceinline__ unsigned supmask16(unsigned r) {
    unsigned w = 0xFFFFu;
    if (r & 1u) w &= 0xAAAAu;
    if (r & 2u) w &= 0xCCCCu;
    if (r & 4u) w &= 0xF0F0u;
    if (r & 8u) w &= 0xFF00u;
    return w;
}

// smem: phase 1: sA (256*4 f32 = 4096B) + sB (256*4 f32 = 4096B)
//       phase 2 (reduction, aliased): 128 threads * 25 u64 = 25600B
#define SMEM_BYTES 25600
#define RSTRIDE 25

__global__ __launch_bounds__(256, 2) void clifford_kernel(
    const float* __restrict__ A,
    const float* __restrict__ B,
    float* __restrict__ out) {
    __shared__ __align__(16) char smem_raw[SMEM_BYTES];
    float* sA = (float*)smem_raw;             // [j*4 + g], (-1)^q(j) folded in
    float* sB = (float*)(smem_raw + 4096);    // [k*4 + g], 16B rows

    const int tid = threadIdx.x;              // 0..255
    const int iL = tid & 63;                  // base i (bits 6,7 = 0)
    const int s = tid >> 6;                   // j-slice 0..3
    const int base = blockIdx.x * G;

    // Coalesced fill; fold (-1)^{q(j)} into A
    #pragma unroll
    for (int r = 0; r < (NCOMP * G) / 256; ++r) {
        int idx = r * 256 + tid;
        int j = idx & (NCOMP - 1);
        int g = idx >> 8;
        float a = A[(base + g) * NCOMP + j];
        unsigned q = (unsigned)__popc(j & (int)ppf((unsigned)j)) & 1u;
        sA[j * 4 + g] = __int_as_float(__float_as_int(a) ^ (int)(q << 31));
        sB[j * 4 + g] = B[(base + g) * NCOMP + j];
    }
    __syncthreads();

    const int i = iL;
    const unsigned pp_i = ppf((unsigned)i);
    const unsigned par_i = (unsigned)__popc(i) & 1u;
    const u64 pis2 = pack2(par_i << 31);
    const u64 neg2 = 0x8000000080000000ULL;

    // 16-bit LUTs over low nibble u
    unsigned lut_s = 0u;                      // bit u = parity(u & pp_i)
    if (pp_i & 1u) lut_s ^= 0xAAAAu;
    if (pp_i & 2u) lut_s ^= 0xCCCCu;
    if (pp_i & 4u) lut_s ^= 0xF0F0u;
    if (pp_i & 8u) lut_s ^= 0xFF00u;

    const int jo = s << 4;                    // bits 4,5 of j
    const unsigned pjo = (unsigned)__popc(jo & (int)pp_i) & 1u;
    const unsigned S_w = pjo ? (lut_s ^ 0xFFFFu) : lut_s;
    const unsigned W_w = (((jo & ~i) & 0x30) == 0) ? submask16((unsigned)i & 15u) : 0u;
    const unsigned C1_w = (((jo & i) & 0x30) == 0) ? submask16((unsigned)(~i) & 15u) : 0u;
    const unsigned C2_w = (((i & ~jo) & 0x30) == 0) ? supmask16((unsigned)i & 15u) : 0u;
    const int koi = jo ^ i;

    u64 Gm[4][2], Wm[4][2], Nm[4][2];
    #pragma unroll
    for (int m = 0; m < 4; ++m)
        #pragma unroll
        for (int p = 0; p < 2; ++p) { Gm[m][p] = 0ull; Wm[m][p] = 0ull; Nm[m][p] = 0ull; }

    #pragma unroll
    for (int u = 0; u < 16; ++u) {            // u compile-time
        const int j = jo | u;
        const int k = koi ^ u;
        const unsigned s32 = ((S_w << (31 - u)) & 0x80000000u) | 0x3f800000u;
        const unsigned wm = (unsigned)(((int)(W_w << (31 - u))) >> 31);
        const unsigned c1m = (unsigned)(((int)(C1_w << (31 - u))) >> 31);
        const unsigned c2m = (unsigned)(((int)(C2_w << (31 - u))) >> 31);
        const u64 s2 = pack2(s32);
        const u64 ws2 = pack2(s32 & wm);
        const u64 n1 = pack2(s32 & c1m);
        const u64 n2 = pack2(s32 & c2m);
        const u64 n12 = pack2(s32 & (c1m | c2m));

        const ulonglong2 A0 = *(const ulonglong2*)(sA + j * 4);
        const ulonglong2 A1 = *(const ulonglong2*)(sA + j * 4 + 256);
        const ulonglong2 A2 = *(const ulonglong2*)(sA + j * 4 + 512);
        const ulonglong2 A3 = *(const ulonglong2*)(sA + j * 4 + 768);
        const ulonglong2 B0 = *(const ulonglong2*)(sB + k * 4);
        const ulonglong2 B1 = *(const ulonglong2*)(sB + k * 4 + 256);
        const ulonglong2 B2 = *(const ulonglong2*)(sB + k * 4 + 512);
        const ulonglong2 B3 = *(const ulonglong2*)(sB + k * 4 + 768);

        #pragma unroll
        for (int p = 0; p < 2; ++p) {
            const u64 a0 = p ? A0.y : A0.x;
            const u64 a1 = (p ? A1.y : A1.x) ^ pis2;   // sign folds (A side)
            const u64 a2 = (p ? A2.y : A2.x) ^ pis2;
            const u64 a3 = (p ? A3.y : A3.x) ^ neg2;
            const u64 b0 = p ? B0.y : B0.x;
            const u64 b1 = p ? B1.y : B1.x;
            const u64 b2 = p ? B2.y : B2.x;
            const u64 b3 = p ? B3.y : B3.x;
            const u64 b1f = b1 ^ neg2;                 // B variants for hi>=2
            const u64 b3f = b3 ^ neg2;

            u64 v00, v01, v02, v03, v10, v11, v12, v13;
            u64 v20, v21, v22, v23, v30, v31, v32, v33;
            MUL2(v00, a0, b0); MUL2(v01, a0, b1); MUL2(v02, a0, b2); MUL2(v03, a0, b3);
            MUL2(v10, a1, b0); MUL2(v11, a1, b1); MUL2(v12, a1, b2); MUL2(v13, a1, b3);
            MUL2(v20, a2, b0); MUL2(v21, a2, b1f); MUL2(v22, a2, b2); MUL2(v23, a2, b3f);
            MUL2(v30, a3, b0); MUL2(v31, a3, b1f); MUL2(v32, a3, b2); MUL2(v33, a3, b3f);

            // geometric: output m = hi ^ hv
            FMA2(Gm[0][p], v00, s2, Gm[0][p]);
            FMA2(Gm[0][p], v11, s2, Gm[0][p]);
            FMA2(Gm[0][p], v22, s2, Gm[0][p]);
            FMA2(Gm[0][p], v33, s2, Gm[0][p]);
            FMA2(Gm[1][p], v01, s2, Gm[1][p]);
            FMA2(Gm[1][p], v10, s2, Gm[1][p]);
            FMA2(Gm[1][p], v23, s2, Gm[1][p]);
            FMA2(Gm[1][p], v32, s2, Gm[1][p]);
            FMA2(Gm[2][p], v02, s2, Gm[2][p]);
            FMA2(Gm[2][p], v13, s2, Gm[2][p]);
            FMA2(Gm[2][p], v20, s2, Gm[2][p]);
            FMA2(Gm[2][p], v31, s2, Gm[2][p]);
            FMA2(Gm[3][p], v03, s2, Gm[3][p]);
            FMA2(Gm[3][p], v12, s2, Gm[3][p]);
            FMA2(Gm[3][p], v21, s2, Gm[3][p]);
            FMA2(Gm[3][p], v30, s2, Gm[3][p]);
            // wedge: active iff hi & hv == 0 (high bits), low via ws2 mask
            FMA2(Wm[0][p], v00, ws2, Wm[0][p]);
            FMA2(Wm[1][p], v01, ws2, Wm[1][p]);
            FMA2(Wm[1][p], v10, ws2, Wm[1][p]);
            FMA2(Wm[2][p], v02, ws2, Wm[2][p]);
            FMA2(Wm[2][p], v20, ws2, Wm[2][p]);
            FMA2(Wm[3][p], v03, ws2, Wm[3][p]);
            FMA2(Wm[3][p], v12, ws2, Wm[3][p]);
            FMA2(Wm[3][p], v21, ws2, Wm[3][p]);
            FMA2(Wm[3][p], v30, ws2, Wm[3][p]);
            // inner: diagonal (m=0) uses c1|c2; off-diag c1 (hi sub hv) or c2 (hv sub hi)
            FMA2(Nm[0][p], v00, n12, Nm[0][p]);
            FMA2(Nm[0][p], v11, n12, Nm[0][p]);
            FMA2(Nm[0][p], v22, n12, Nm[0][p]);
            FMA2(Nm[0][p], v33, n12, Nm[0][p]);
            FMA2(Nm[1][p], v01, n1, Nm[1][p]);
            FMA2(Nm[1][p], v23, n1, Nm[1][p]);
            FMA2(Nm[1][p], v10, n2, Nm[1][p]);
            FMA2(Nm[1][p], v32, n2, Nm[1][p]);
            FMA2(Nm[2][p], v02, n1, Nm[2][p]);
            FMA2(Nm[2][p], v13, n1, Nm[2][p]);
            FMA2(Nm[2][p], v20, n2, Nm[2][p]);
            FMA2(Nm[2][p], v31, n2, Nm[2][p]);
            FMA2(Nm[3][p], v03, n1, Nm[3][p]);
            FMA2(Nm[3][p], v30, n2, Nm[3][p]);
        }
    }

    // Tree reduction across the 4 j-slices (smem aliased over sA/sB)
    __syncthreads();
    u64* red = (u64*)smem_raw;

    if (tid >= 128) {                              // slices 2,3 store
        u64* dst = red + (tid - 128) * RSTRIDE;
        #pragma unroll
        for (int m = 0; m < 4; ++m)
            #pragma unroll
            for (int p = 0; p < 2; ++p) {
                dst[m * 2 + p] = Gm[m][p];
                dst[8 + m * 2 + p] = Wm[m][p];
                dst[16 + m * 2 + p] = Nm[m][p];
            }
    }
    __syncthreads();
    if (tid < 128) {                               // slices 0,1 add
        const u64* src = red + tid * RSTRIDE;
        #pragma unroll
        for (int m = 0; m < 4; ++m)
            #pragma unroll
            for (int p = 0; p < 2; ++p) {
                ADD2(Gm[m][p], Gm[m][p], src[m * 2 + p]);
                ADD2(Wm[m][p], Wm[m][p], src[8 + m * 2 + p]);
                ADD2(Nm[m][p], Nm[m][p], src[16 + m * 2 + p]);
            }
    }
    __syncthreads();
    if (tid >= 64 && tid < 128) {                  // slice 1 stores
        u64* dst = red + (tid - 64) * RSTRIDE;
        #pragma unroll
        for (int m = 0; m < 4; ++m)
            #pragma unroll
            for (int p = 0; p < 2; ++p) {
                dst[m * 2 + p] = Gm[m][p];
                dst[8 + m * 2 + p] = Wm[m][p];
                dst[16 + m * 2 + p] = Nm[m][p];
            }
    }
    __syncthreads();
    if (tid < 64) {                                // slice 0 adds + writes
        const u64* src = red + tid * RSTRIDE;
        #pragma unroll
        for (int m = 0; m < 4; ++m)
            #pragma unroll
            for (int p = 0; p < 2; ++p) {
                ADD2(Gm[m][p], Gm[m][p], src[m * 2 + p]);
                ADD2(Wm[m][p], Wm[m][p], src[8 + m * 2 + p]);
                ADD2(Nm[m][p], Nm[m][p], src[16 + m * 2 + p]);
            }
        #pragma unroll
        for (int m = 0; m < 4; ++m) {
            const int im = iL | (m << 6);
            #pragma unroll
            for (int p = 0; p < 2; ++p) {
                const int be0 = base + 2 * p;
                float2 g = unpack2(Gm[m][p]);
                float2 w = unpack2(Wm[m][p]);
                float2 n = unpack2(Nm[m][p]);
                out[(0 * BATCH_ELEMS + be0) * NCOMP + im] = g.x;
                out[(0 * BATCH_ELEMS + be0 + 1) * NCOMP + im] = g.y;
                out[(1 * BATCH_ELEMS + be0) * NCOMP + im] = w.x;
                out[(1 * BATCH_ELEMS + be0 + 1) * NCOMP + im] = w.y;
                out[(2 * BATCH_ELEMS + be0) * NCOMP + im] = n.x;
                out[(2 * BATCH_ELEMS + be0 + 1) * NCOMP + im] = n.y;
            }
        }
    }
}

extern "C" void kernel_launch(void* const* d_in, const int* in_sizes, int n_in,
                              void* d_out, int out_size) {
    const float* A = (const float*)d_in[0];
    const float* B = (const float*)d_in[1];
    float* out = (float*)d_out;
    clifford_kernel<<<BATCH_ELEMS / G, 256>>>(A, B, out);
}

// round 12
// speedup vs baseline: 1.9870x; 1.0173x over previous
#include <cuda_runtime.h>
#include <stdint.h>

// Cl(8,0,0): 256 comps, 1024 multivectors (4x256), out [3,1024,256].
// 4x4 XOR tiling on bits 6,7 (see R11): 16 products per 4 A + 4 B row loads.
// Recut for residency: 128-thr blocks (32 iL x 4 j-slices), grid 512 ->
// whole grid resident in one wave (4 blocks/SM at ~104 regs).
// G=4 batch elems, f32x2 math, smem tree reduction across slices.

#define NCOMP 256
#define G 4
#define BATCH_ELEMS 1024

typedef unsigned long long u64;

#define MUL2(out, a, b) \
    asm("mul.rn.f32x2 %0, %1, %2;" : "=l"(out) : "l"(a), "l"(b))
#define FMA2(out, a, b, c) \
    asm("fma.rn.f32x2 %0, %1, %2, %3;" : "=l"(out) : "l"(a), "l"(b), "l"(c))
#define ADD2(out, a, b) \
    asm("add.rn.f32x2 %0, %1, %2;" : "=l"(out) : "l"(a), "l"(b))

__device__ __forceinline__ u64 pack2(unsigned w) {
    u64 r;
    asm("mov.b64 %0, {%1, %1};" : "=l"(r) : "r"(w));
    return r;
}
__device__ __forceinline__ float2 unpack2(u64 v) {
    float2 f;
    asm("mov.b64 {%0, %1}, %2;" : "=f"(f.x), "=f"(f.y) : "l"(v));
    return f;
}

__host__ __device__ __forceinline__ constexpr unsigned ppf(unsigned v) {
    unsigned x = v << 1;
    x ^= x << 1;
    x ^= x << 2;
    x ^= x << 4;
    return x & 0xffu;
}

__device__ __forceinline__ unsigned submask16(unsigned m) {
    unsigned w = 1u;
    if (m & 1u) w |= w << 1;
    if (m & 2u) w |= w << 2;
    if (m & 4u) w |= w << 4;
    if (m & 8u) w |= w << 8;
    return w;
}
__device__ __forceinline__ unsigned supmask16(unsigned r) {
    unsigned w = 0xFFFFu;
    if (r & 1u) w &= 0xAAAAu;
    if (r & 2u) w &= 0xCCCCu;
    if (r & 4u) w &= 0xF0F0u;
    if (r & 8u) w &= 0xFF00u;
    return w;
}

// smem: phase 1: sA (256*4 f32 = 4096B) + sB (256*4 f32 = 4096B) = 8192B
//       phase 2 (reduction, aliased): 64 threads * 25 u64 = 12800B
#define SMEM_BYTES 12800
#define RSTRIDE 25

__global__ __launch_bounds__(128, 4) void clifford_kernel(
    const float* __restrict__ A,
    const float* __restrict__ B,
    float* __restrict__ out) {
    __shared__ __align__(16) char smem_raw[SMEM_BYTES];
    float* sA = (float*)smem_raw;             // [j*4 + g], (-1)^q(j) folded in
    float* sB = (float*)(smem_raw + 4096);    // [k*4 + g], 16B rows

    const int tid = threadIdx.x;              // 0..127
    const int s = tid >> 5;                   // j-slice 0..3
    const int iq = blockIdx.x & 1;            // iL half
    const int iL = iq * 32 + (tid & 31);      // base i (bits 6,7 = 0)
    const int base = (blockIdx.x >> 1) * G;

    // Coalesced fill; fold (-1)^{q(j)} into A
    #pragma unroll
    for (int r = 0; r < (NCOMP * G) / 128; ++r) {
        int idx = r * 128 + tid;
        int j = idx & (NCOMP - 1);
        int g = idx >> 8;
        float a = A[(base + g) * NCOMP + j];
        unsigned q = (unsigned)__popc(j & (int)ppf((unsigned)j)) & 1u;
        sA[j * 4 + g] = __int_as_float(__float_as_int(a) ^ (int)(q << 31));
        sB[j * 4 + g] = B[(base + g) * NCOMP + j];
    }
    __syncthreads();

    const int i = iL;
    const unsigned pp_i = ppf((unsigned)i);
    const unsigned par_i = (unsigned)__popc(i) & 1u;
    const u64 pis2 = pack2(par_i << 31);
    const u64 neg2 = 0x8000000080000000ULL;

    // 16-bit LUTs over low nibble u
    unsigned lut_s = 0u;                      // bit u = parity(u & pp_i)
    if (pp_i & 1u) lut_s ^= 0xAAAAu;
    if (pp_i & 2u) lut_s ^= 0xCCCCu;
    if (pp_i & 4u) lut_s ^= 0xF0F0u;
    if (pp_i & 8u) lut_s ^= 0xFF00u;

    const int jo = s << 4;                    // bits 4,5 of j
    const unsigned pjo = (unsigned)__popc(jo & (int)pp_i) & 1u;
    const unsigned S_w = pjo ? (lut_s ^ 0xFFFFu) : lut_s;
    const unsigned W_w = (((jo & ~i) & 0x30) == 0) ? submask16((unsigned)i & 15u) : 0u;
    const unsigned C1_w = (((jo & i) & 0x30) == 0) ? submask16((unsigned)(~i) & 15u) : 0u;
    const unsigned C2_w = (((i & ~jo) & 0x30) == 0) ? supmask16((unsigned)i & 15u) : 0u;
    const int koi = jo ^ i;

    u64 Gm[4][2], Wm[4][2], Nm[4][2];
    #pragma unroll
    for (int m = 0; m < 4; ++m)
        #pragma unroll
        for (int p = 0; p < 2; ++p) { Gm[m][p] = 0ull; Wm[m][p] = 0ull; Nm[m][p] = 0ull; }

    #pragma unroll
    for (int u = 0; u < 16; ++u) {            // u compile-time
        const int j = jo | u;
        const int k = koi ^ u;
        const unsigned s32 = ((S_w << (31 - u)) & 0x80000000u) | 0x3f800000u;
        const unsigned wm = (unsigned)(((int)(W_w << (31 - u))) >> 31);
        const unsigned c1m = (unsigned)(((int)(C1_w << (31 - u))) >> 31);
        const unsigned c2m = (unsigned)(((int)(C2_w << (31 - u))) >> 31);
        const u64 s2 = pack2(s32);
        const u64 ws2 = pack2(s32 & wm);
        const u64 n1 = pack2(s32 & c1m);
        const u64 n2 = pack2(s32 & c2m);
        const u64 n12 = pack2(s32 & (c1m | c2m));

        const ulonglong2 A0 = *(const ulonglong2*)(sA + j * 4);
        const ulonglong2 A1 = *(const ulonglong2*)(sA + j * 4 + 256);
        const ulonglong2 A2 = *(const ulonglong2*)(sA + j * 4 + 512);
        const ulonglong2 A3 = *(const ulonglong2*)(sA + j * 4 + 768);
        const ulonglong2 B0 = *(const ulonglong2*)(sB + k * 4);
        const ulonglong2 B1 = *(const ulonglong2*)(sB + k * 4 + 256);
        const ulonglong2 B2 = *(const ulonglong2*)(sB + k * 4 + 512);
        const ulonglong2 B3 = *(const ulonglong2*)(sB + k * 4 + 768);

        #pragma unroll
        for (int p = 0; p < 2; ++p) {
            const u64 a0 = p ? A0.y : A0.x;
            const u64 a1 = (p ? A1.y : A1.x) ^ pis2;   // sign folds (A side)
            const u64 a2 = (p ? A2.y : A2.x) ^ pis2;
            const u64 a3 = (p ? A3.y : A3.x) ^ neg2;
            const u64 b0 = p ? B0.y : B0.x;
            const u64 b1 = p ? B1.y : B1.x;
            const u64 b2 = p ? B2.y : B2.x;
            const u64 b3 = p ? B3.y : B3.x;
            const u64 b1f = b1 ^ neg2;                 // B variants for hi>=2
            const u64 b3f = b3 ^ neg2;

            u64 v00, v01, v02, v03, v10, v11, v12, v13;
            u64 v20, v21, v22, v23, v30, v31, v32, v33;
            MUL2(v00, a0, b0); MUL2(v01, a0, b1); MUL2(v02, a0, b2); MUL2(v03, a0, b3);
            MUL2(v10, a1, b0); MUL2(v11, a1, b1); MUL2(v12, a1, b2); MUL2(v13, a1, b3);
            MUL2(v20, a2, b0); MUL2(v21, a2, b1f); MUL2(v22, a2, b2); MUL2(v23, a2, b3f);
            MUL2(v30, a3, b0); MUL2(v31, a3, b1f); MUL2(v32, a3, b2); MUL2(v33, a3, b3f);

            // geometric: output m = hi ^ hv
            FMA2(Gm[0][p], v00, s2, Gm[0][p]);
            FMA2(Gm[0][p], v11, s2, Gm[0][p]);
            FMA2(Gm[0][p], v22, s2, Gm[0][p]);
            FMA2(Gm[0][p], v33, s2, Gm[0][p]);
            FMA2(Gm[1][p], v01, s2, Gm[1][p]);
            FMA2(Gm[1][p], v10, s2, Gm[1][p]);
            FMA2(Gm[1][p], v23, s2, Gm[1][p]);
            FMA2(Gm[1][p], v32, s2, Gm[1][p]);
            FMA2(Gm[2][p], v02, s2, Gm[2][p]);
            FMA2(Gm[2][p], v13, s2, Gm[2][p]);
            FMA2(Gm[2][p], v20, s2, Gm[2][p]);
            FMA2(Gm[2][p], v31, s2, Gm[2][p]);
            FMA2(Gm[3][p], v03, s2, Gm[3][p]);
            FMA2(Gm[3][p], v12, s2, Gm[3][p]);
            FMA2(Gm[3][p], v21, s2, Gm[3][p]);
            FMA2(Gm[3][p], v30, s2, Gm[3][p]);
            // wedge: active iff hi & hv == 0 (high bits), low via ws2 mask
            FMA2(Wm[0][p], v00, ws2, Wm[0][p]);
            FMA2(Wm[1][p], v01, ws2, Wm[1][p]);
            FMA2(Wm[1][p], v10, ws2, Wm[1][p]);
            FMA2(Wm[2][p], v02, ws2, Wm[2][p]);
            FMA2(Wm[2][p], v20, ws2, Wm[2][p]);
            FMA2(Wm[3][p], v03, ws2, Wm[3][p]);
            FMA2(Wm[3][p], v12, ws2, Wm[3][p]);
            FMA2(Wm[3][p], v21, ws2, Wm[3][p]);
            FMA2(Wm[3][p], v30, ws2, Wm[3][p]);
            // inner: diagonal c1|c2; off-diag c1 (hi sub hv) or c2 (hv sub hi)
            FMA2(Nm[0][p], v00, n12, Nm[0][p]);
            FMA2(Nm[0][p], v11, n12, Nm[0][p]);
            FMA2(Nm[0][p], v22, n12, Nm[0][p]);
            FMA2(Nm[0][p], v33, n12, Nm[0][p]);
            FMA2(Nm[1][p], v01, n1, Nm[1][p]);
            FMA2(Nm[1][p], v23, n1, Nm[1][p]);
            FMA2(Nm[1][p], v10, n2, Nm[1][p]);
            FMA2(Nm[1][p], v32, n2, Nm[1][p]);
            FMA2(Nm[2][p], v02, n1, Nm[2][p]);
            FMA2(Nm[2][p], v13, n1, Nm[2][p]);
            FMA2(Nm[2][p], v20, n2, Nm[2][p]);
            FMA2(Nm[2][p], v31, n2, Nm[2][p]);
            FMA2(Nm[3][p], v03, n1, Nm[3][p]);
            FMA2(Nm[3][p], v30, n2, Nm[3][p]);
        }
    }

    // Tree reduction across the 4 j-slices (smem aliased over sA/sB)
    __syncthreads();
    u64* red = (u64*)smem_raw;

    if (tid >= 64) {                               // slices 2,3 store
        u64* dst = red + (tid - 64) * RSTRIDE;
        #pragma unroll
        for (int m = 0; m < 4; ++m)
            #pragma unroll
            for (int p = 0; p < 2; ++p) {
                dst[m * 2 + p] = Gm[m][p];
                dst[8 + m * 2 + p] = Wm[m][p];
                dst[16 + m * 2 + p] = Nm[m][p];
            }
    }
    __syncthreads();
    if (tid < 64) {                                // slices 0,1 add
        const u64* src = red + tid * RSTRIDE;
        #pragma unroll
        for (int m = 0; m < 4; ++m)
            #pragma unroll
            for (int p = 0; p < 2; ++p) {
                ADD2(Gm[m][p], Gm[m][p], src[m * 2 + p]);
                ADD2(Wm[m][p], Wm[m][p], src[8 + m * 2 + p]);
                ADD2(Nm[m][p], Nm[m][p], src[16 + m * 2 + p]);
            }
    }
    __syncthreads();
    if (tid >= 32 && tid < 64) {                   // slice 1 stores
        u64* dst = red + (tid - 32) * RSTRIDE;
        #pragma unroll
        for (int m = 0; m < 4; ++m)
            #pragma unroll
            for (int p = 0; p < 2; ++p) {
                dst[m * 2 + p] = Gm[m][p];
                dst[8 + m * 2 + p] = Wm[m][p];
                dst[16 + m * 2 + p] = Nm[m][p];
            }
    }
    __syncthreads();
    if (tid < 32) {                                // slice 0 adds + writes
        const u64* src = red + tid * RSTRIDE;
        #pragma unroll
        for (int m = 0; m < 4; ++m)
            #pragma unroll
            for (int p = 0; p < 2; ++p) {
                ADD2(Gm[m][p], Gm[m][p], src[m * 2 + p]);
                ADD2(Wm[m][p], Wm[m][p], src[8 + m * 2 + p]);
                ADD2(Nm[m][p], Nm[m][p], src[16 + m * 2 + p]);
            }
        #pragma unroll
        for (int m = 0; m < 4; ++m) {
            const int im = iL | (m << 6);
            #pragma unroll
            for (int p = 0; p < 2; ++p) {
                const int be0 = base + 2 * p;
                float2 g = unpack2(Gm[m][p]);
                float2 w = unpack2(Wm[m][p]);
                float2 n = unpack2(Nm[m][p]);
                out[(0 * BATCH_ELEMS + be0) * NCOMP + im] = g.x;
                out[(0 * BATCH_ELEMS + be0 + 1) * NCOMP + im] = g.y;
                out[(1 * BATCH_ELEMS + be0) * NCOMP + im] = w.x;
                out[(1 * BATCH_ELEMS + be0 + 1) * NCOMP + im] = w.y;
                out[(2 * BATCH_ELEMS + be0) * NCOMP + im] = n.x;
                out[(2 * BATCH_ELEMS + be0 + 1) * NCOMP + im] = n.y;
            }
        }
    }
}

extern "C" void kernel_launch(void* const* d_in, const int* in_sizes, int n_in,
                              void* d_out, int out_size) {
    const float* A = (const float*)d_in[0];
    const float* B = (const float*)d_in[1];
    float* out = (float*)d_out;
    clifford_kernel<<<(BATCH_ELEMS / G) * 2, 128>>>(A, B, out);
}